// round 12
// baseline (speedup 1.0000x reference)
#include <cuda_runtime.h>
#include <cuda_fp16.h>
#include <cstdint>

#define Hh 8
#define LN_EPS 1e-5f
#define SCALE 0.04419417382415922f  // 512^-0.5 (full C, as in source)

// ---------------- scratch (device globals) ----------------------------------
__device__ __half g_wh[(size_t)3 * 512 * 512];    // fp16 wq|wk|wv
__device__ __half g_qh[(size_t)256 * 512 * 64];   // (b,h,l,d)
__device__ __half g_kh[(size_t)256 * 512 * 64];   // (b,h,l,d)
__device__ __half g_vh[(size_t)256 * 64 * 512];   // (b,h,d,l) transposed V
__device__ __half g_prelnh[(size_t)16384 * 512];  // fp16 pre-LN intermediate

// ---------------- helpers ---------------------------------------------------
__device__ __forceinline__ uint32_t s2u(const void* p) {
    uint32_t a;
    asm("{ .reg .u64 t; cvta.to.shared.u64 t, %1; cvt.u32.u64 %0, t; }" : "=r"(a) : "l"(p));
    return a;
}
__device__ __forceinline__ void cpa16(uint32_t s, const void* g) {
    asm volatile("cp.async.cg.shared.global [%0], [%1], 16;" :: "r"(s), "l"(g));
}
__device__ __forceinline__ void cpa_commit() { asm volatile("cp.async.commit_group;" ::: "memory"); }
template <int N>
__device__ __forceinline__ void cpa_wait() { asm volatile("cp.async.wait_group %0;" :: "n"(N) : "memory"); }

__device__ __forceinline__ void ldm4(uint32_t (&r)[4], uint32_t addr) {
    asm volatile("ldmatrix.sync.aligned.m8n8.x4.shared.b16 {%0,%1,%2,%3}, [%4];"
                 : "=r"(r[0]), "=r"(r[1]), "=r"(r[2]), "=r"(r[3]) : "r"(addr));
}
__device__ __forceinline__ void mma16(float (&c)[4], const uint32_t (&a)[4], const uint32_t* b) {
    asm volatile(
        "mma.sync.aligned.m16n8k16.row.col.f32.f16.f16.f32 "
        "{%0,%1,%2,%3}, {%4,%5,%6,%7}, {%8,%9}, {%0,%1,%2,%3};"
        : "+f"(c[0]), "+f"(c[1]), "+f"(c[2]), "+f"(c[3])
        : "r"(a[0]), "r"(a[1]), "r"(a[2]), "r"(a[3]), "r"(b[0]), "r"(b[1]));
}

// ---------------- Kernel 0: fp16 convert of WEIGHTS only ---------------------
__global__ __launch_bounds__(256) void cvt_w_kernel(
    const float* __restrict__ wq, const float* __restrict__ wk,
    const float* __restrict__ wv)
{
    int idx = blockIdx.x * 256 + threadIdx.x;   // 8-float group
    const int WG = 512 * 512 / 8;               // 32768
    int w = idx / WG, r = idx - w * WG;
    const float* s = (w == 0) ? wq : (w == 1) ? wk : wv;
    const float4* src = (const float4*)s + (size_t)r * 2;
    __half* dst = g_wh + ((size_t)w * WG + r) * 8;
    float4 a = src[0], b = src[1];
    __half2 h0 = __float22half2_rn(make_float2(a.x, a.y));
    __half2 h1 = __float22half2_rn(make_float2(a.z, a.w));
    __half2 h2 = __float22half2_rn(make_float2(b.x, b.y));
    __half2 h3 = __float22half2_rn(make_float2(b.z, b.w));
    uint4 o = make_uint4(*(uint32_t*)&h0, *(uint32_t*)&h1, *(uint32_t*)&h2, *(uint32_t*)&h3);
    *(uint4*)dst = o;
}

// ---------------- Kernel 1: QKV projection (fused fp32 A convert) ------------
// CTA 128x128, 8 warps (2m x 4n), warp tile 64x32. K-chunk 32.
// A: fp32 x -> cp.async staging (x3) -> in-kernel convert -> fp16 tile (x2).
// B: fp16 weights via cp.async (x3). 16 chunks.
// smem: a16 2x10240 @0 | b16 3x10240 @20480 | staging 3x16384 @51200 = 100352 B
#define QKV_SMEM 100352
#define A16_OFF  0
#define B16_OFF  20480
#define STG_OFF  51200
__global__ __launch_bounds__(256, 2) void qkv_g(const float* __restrict__ x)
{
    extern __shared__ char smc[];
    __half* smh = (__half*)smc;
    const uint32_t sb = s2u(smc);
    const int tid = threadIdx.x;
    const int lane = tid & 31, warp = tid >> 5;
    const int wm = warp & 1, wn = warp >> 1;
    const int g = lane >> 2, t4 = lane & 3;
    const int which = blockIdx.z;
    const int m0 = blockIdx.y * 128;
    const int n0 = blockIdx.x * 128;

    const float* __restrict__ A = x + (size_t)m0 * 512;
    const __half* __restrict__ B = g_wh + (size_t)which * 262144 + (size_t)n0 * 512;

    const uint32_t a_base = (uint32_t)(((wm * 64 + (lane & 15)) * 40 + (lane >> 4) * 8) * 2);
    const uint32_t b_frag = (uint32_t)((((lane & 7) + (lane >> 4) * 8 + wn * 32) * 40
                                       + ((lane >> 3) & 1) * 8) * 2);

    float acc[4][4][4];
#pragma unroll
    for (int mi = 0; mi < 4; ++mi)
#pragma unroll
        for (int ni = 0; ni < 4; ++ni)
#pragma unroll
            for (int r = 0; r < 4; ++r) acc[mi][ni][r] = 0.f;

    auto load_chunk = [&](int c, int buf3) {
        // A fp32 (128x32 floats -> 16384 B)
        uint32_t sA = sb + (uint32_t)(STG_OFF + buf3 * 16384);
#pragma unroll
        for (int i = 0; i < 4; ++i) {
            int idx = tid + i * 256;
            int r = idx >> 3, sg = idx & 7;
            cpa16(sA + (uint32_t)(r * 128 + sg * 16),
                  A + (size_t)r * 512 + c * 32 + sg * 4);
        }
        // B fp16 (128x32 halves, stride 40)
        uint32_t sB = sb + (uint32_t)(B16_OFF + buf3 * 10240);
#pragma unroll
        for (int i = 0; i < 2; ++i) {
            int idx = tid + i * 256;
            int r = idx >> 2, sg = idx & 3;
            cpa16(sB + (uint32_t)(r * 80 + sg * 16),
                  B + (size_t)r * 512 + c * 32 + sg * 8);
        }
        cpa_commit();
    };

    load_chunk(0, 0);
    load_chunk(1, 1);

    const int cr = tid >> 1, chf = tid & 1;   // convert: row, 16-col half

    for (int c = 0; c < 16; ++c) {
        cpa_wait<1>();
        __syncthreads();

        // convert staging[c%3] fp32 -> a16[c%2] (stride 40 halves)
        {
            const float* stg = (const float*)(smc + STG_OFF + (c % 3) * 16384);
            __half* adst = (__half*)(smc + A16_OFF + (c % 2) * 10240);
            const float* srow = stg + cr * 32 + chf * 16;
            float4 f0 = *(const float4*)(srow);
            float4 f1 = *(const float4*)(srow + 4);
            float4 f2 = *(const float4*)(srow + 8);
            float4 f3 = *(const float4*)(srow + 12);
            __half2 h0 = __float22half2_rn(make_float2(f0.x, f0.y));
            __half2 h1 = __float22half2_rn(make_float2(f0.z, f0.w));
            __half2 h2 = __float22half2_rn(make_float2(f1.x, f1.y));
            __half2 h3 = __float22half2_rn(make_float2(f1.z, f1.w));
            __half2 h4 = __float22half2_rn(make_float2(f2.x, f2.y));
            __half2 h5 = __float22half2_rn(make_float2(f2.z, f2.w));
            __half2 h6 = __float22half2_rn(make_float2(f3.x, f3.y));
            __half2 h7 = __float22half2_rn(make_float2(f3.z, f3.w));
            uint4 o0 = make_uint4(*(uint32_t*)&h0, *(uint32_t*)&h1,
                                  *(uint32_t*)&h2, *(uint32_t*)&h3);
            uint4 o1 = make_uint4(*(uint32_t*)&h4, *(uint32_t*)&h5,
                                  *(uint32_t*)&h6, *(uint32_t*)&h7);
            *(uint4*)(adst + cr * 40 + chf * 16) = o0;
            *(uint4*)(adst + cr * 40 + chf * 16 + 8) = o1;
        }
        __syncthreads();

        if (c + 2 < 16) load_chunk(c + 2, (c + 2) % 3);
        else cpa_commit();   // keep group counting uniform

        uint32_t sa = sb + (uint32_t)(A16_OFF + (c % 2) * 10240);
        uint32_t skb = sb + (uint32_t)(B16_OFF + (c % 3) * 10240);
#pragma unroll
        for (int ks = 0; ks < 2; ++ks) {
            const uint32_t ko = (uint32_t)(ks * 32);   // 16 halves
            uint32_t af[4][4], bf0[4], bf1[4];
#pragma unroll
            for (int mi = 0; mi < 4; ++mi)
                ldm4(af[mi], sa + a_base + (uint32_t)(mi * 1280) + ko);
            ldm4(bf0, skb + b_frag + ko);
            ldm4(bf1, skb + b_frag + (uint32_t)(16 * 80) + ko);
#pragma unroll
            for (int mi = 0; mi < 4; ++mi) {
                mma16(acc[mi][0], af[mi], &bf0[0]);
                mma16(acc[mi][1], af[mi], &bf0[2]);
                mma16(acc[mi][2], af[mi], &bf1[0]);
                mma16(acc[mi][3], af[mi], &bf1[2]);
            }
        }
        __syncthreads();
    }

    __half* sT = smh;   // 128 x 136 staging tile (34816 B, fits)
    if (which <= 1) {
#pragma unroll
        for (int mi = 0; mi < 4; ++mi) {
#pragma unroll
            for (int ni = 0; ni < 4; ++ni) {
                int nl = wn * 32 + ni * 8 + 2 * t4;
                int ml = wm * 64 + mi * 16 + g;
                *(__half2*)&sT[ml * 136 + nl] =
                    __float22half2_rn(make_float2(acc[mi][ni][0], acc[mi][ni][1]));
                *(__half2*)&sT[(ml + 8) * 136 + nl] =
                    __float22half2_rn(make_float2(acc[mi][ni][2], acc[mi][ni][3]));
            }
        }
        __syncthreads();
        __half* out = (which == 0) ? g_qh : g_kh;
        int b = m0 >> 9, l0 = m0 & 511;
#pragma unroll
        for (int i = 0; i < 8; ++i) {
            int f = tid + i * 256;
            int row = f >> 4, seg = f & 15;
            uint4 v = *(const uint4*)&sT[row * 136 + seg * 8];
            int h = (n0 >> 6) + (seg >> 3);
            int d = (seg & 7) * 8;
            *(uint4*)&out[((size_t)(b * 8 + h) * 512 + l0 + row) * 64 + d] = v;
        }
    } else {
#pragma unroll
        for (int mi = 0; mi < 4; ++mi) {
#pragma unroll
            for (int ni = 0; ni < 4; ++ni) {
                int nl = wn * 32 + ni * 8 + 2 * t4;
                int ml = wm * 64 + mi * 16 + g;
                sT[nl * 136 + ml]           = __float2half_rn(acc[mi][ni][0]);
                sT[(nl + 1) * 136 + ml]     = __float2half_rn(acc[mi][ni][1]);
                sT[nl * 136 + ml + 8]       = __float2half_rn(acc[mi][ni][2]);
                sT[(nl + 1) * 136 + ml + 8] = __float2half_rn(acc[mi][ni][3]);
            }
        }
        __syncthreads();
        int b = m0 >> 9, l0 = m0 & 511;
#pragma unroll
        for (int i = 0; i < 8; ++i) {
            int f = tid + i * 256;
            int row = f >> 4, seg = f & 15;
            uint4 v = *(const uint4*)&sT[row * 136 + seg * 8];
            int n = n0 + row, h = n >> 6, d = n & 63;
            *(uint4*)&g_vh[(((size_t)(b * 8 + h)) * 64 + d) * 512 + l0 + seg * 8] = v;
        }
    }
}

// ---------------- Kernel 2: fused attention (fp16 S, occupancy 2) ------------
#define ATT_SMEM 114944
#define SS_OFF   9216
#define SKV_OFF  75776
#define SB_OFF   112640
__global__ __launch_bounds__(256, 2) void attn_g(const float* __restrict__ bias_table)
{
    extern __shared__ char smc[];
    const uint32_t sb = s2u(smc);
    const int tid = threadIdx.x;
    const int lane = tid & 31, warp = tid >> 5;
    const int wm = warp & 1, wn = warp >> 1;
    const int g = lane >> 2, t4 = lane & 3;
    const int qb = blockIdx.x;
    const int bh = blockIdx.y;
    const int b = bh >> 3, h = bh & 7;

    const __half* __restrict__ gq = g_qh + (size_t)bh * 32768 + (size_t)qb * 64 * 64;
    const __half* __restrict__ gk = g_kh + (size_t)bh * 32768;
    const __half* __restrict__ gv = g_vh + (size_t)bh * 32768;

    const uint32_t sQ = sb;
    const uint32_t sSb = sb + SS_OFF;
    const uint32_t sKV = sb + SKV_OFF;
    __half* sSh = (__half*)(smc + SS_OFF);
    float* sbias = (float*)(smc + SB_OFF);
    const int woff = 448 - qb * 64;

#pragma unroll
    for (int i = 0; i < 2; ++i) {
        int idx = tid + i * 256;
        int r = idx >> 3, sg = idx & 7;
        cpa16(sQ + (uint32_t)((r * 72 + sg * 8) * 2), gq + (size_t)r * 64 + sg * 8);
    }
#pragma unroll
    for (int i = 0; i < 3; ++i) {
        int j = tid + i * 256;
        if (j < 575) sbias[j] = bias_table[(size_t)(j + woff) * 8 + h];
    }
    cpa_commit();

    auto load_k = [&](int c, int buf) {
        uint32_t base = sKV + (uint32_t)(buf * 18432);
        const __half* src = gk + (size_t)c * 128 * 64;
#pragma unroll
        for (int i = 0; i < 4; ++i) {
            int idx = tid + i * 256;
            int r = idx >> 3, sg = idx & 7;
            cpa16(base + (uint32_t)((r * 72 + sg * 8) * 2), src + (size_t)r * 64 + sg * 8);
        }
    };
    load_k(0, 0);
    cpa_commit();

    const uint32_t aq_base = (uint32_t)(((wm * 32 + (lane & 15)) * 72 + (lane >> 4) * 8) * 2);
    const uint32_t bk_base = (uint32_t)((((lane & 7) + (lane >> 4) * 8 + wn * 32) * 72
                                        + ((lane >> 3) & 1) * 8) * 2);

    for (int c = 0; c < 4; ++c) {
        if (c + 1 < 4) load_k(c + 1, (c + 1) & 1);
        cpa_commit();
        cpa_wait<1>();
        __syncthreads();
        uint32_t skb = sKV + (uint32_t)((c & 1) * 18432);

        float acc[2][4][4];
#pragma unroll
        for (int mi = 0; mi < 2; ++mi)
#pragma unroll
            for (int ni = 0; ni < 4; ++ni)
#pragma unroll
                for (int r = 0; r < 4; ++r) acc[mi][ni][r] = 0.f;

#pragma unroll
        for (int ks = 0; ks < 4; ++ks) {
            const uint32_t ko = (uint32_t)(ks * 32);
            uint32_t af[2][4], bf0[4], bf1[4];
            ldm4(af[0], sQ + aq_base + ko);
            ldm4(af[1], sQ + aq_base + (uint32_t)(16 * 72 * 2) + ko);
            ldm4(bf0, skb + bk_base + ko);
            ldm4(bf1, skb + bk_base + (uint32_t)(16 * 72 * 2) + ko);
#pragma unroll
            for (int mi = 0; mi < 2; ++mi) {
                mma16(acc[mi][0], af[mi], &bf0[0]);
                mma16(acc[mi][1], af[mi], &bf0[2]);
                mma16(acc[mi][2], af[mi], &bf1[0]);
                mma16(acc[mi][3], af[mi], &bf1[2]);
            }
        }
#pragma unroll
        for (int mi = 0; mi < 2; ++mi) {
#pragma unroll
            for (int ni = 0; ni < 4; ++ni) {
                int ml = wm * 32 + mi * 16 + g;
                int col = c * 128 + wn * 32 + ni * 8 + 2 * t4;
                *(__half2*)&sSh[ml * 520 + col] =
                    __float22half2_rn(make_float2(acc[mi][ni][0] * SCALE, acc[mi][ni][1] * SCALE));
                *(__half2*)&sSh[(ml + 8) * 520 + col] =
                    __float22half2_rn(make_float2(acc[mi][ni][2] * SCALE, acc[mi][ni][3] * SCALE));
            }
        }
        __syncthreads();
    }

    auto load_v = [&](int c, int buf) {
        uint32_t base = sKV + (uint32_t)(buf * 18432);
        const __half* src = gv + (size_t)c * 128;
#pragma unroll
        for (int i = 0; i < 4; ++i) {
            int idx = tid + i * 256;
            int r = idx >> 4, sg = idx & 15;
            cpa16(base + (uint32_t)((r * 136 + sg * 8) * 2), src + (size_t)r * 512 + sg * 8);
        }
    };
    load_v(0, 0);
    cpa_commit();

    // softmax (no max-sub: |s| < 1) + post-softmax bias; P fp16 in-place
    {
        const int r0 = warp * 8;
#pragma unroll
        for (int rr = 0; rr < 8; ++rr) {
            const int r = r0 + rr;
            __half2* rowh = (__half2*)(sSh + (size_t)r * 520);
            float vals[16];
            float s = 0.f;
#pragma unroll
            for (int jj = 0; jj < 8; ++jj) {
                float2 fv = __half22float2(rowh[lane + 32 * jj]);
                vals[2 * jj]     = __expf(fv.x);
                vals[2 * jj + 1] = __expf(fv.y);
                s += vals[2 * jj] + vals[2 * jj + 1];
            }
#pragma unroll
            for (int o = 16; o > 0; o >>= 1) s += __shfl_xor_sync(0xffffffffu, s, o);
            float inv = 1.f / s;
            int bbase = 63 - r;
#pragma unroll
            for (int jj = 0; jj < 8; ++jj) {
                int col = 2 * lane + 64 * jj;
                float2 p;
                p.x = vals[2 * jj]     * inv + sbias[bbase + col];
                p.y = vals[2 * jj + 1] * inv + sbias[bbase + col + 1];
                rowh[lane + 32 * jj] = __float22half2_rn(p);
            }
        }
    }
    __syncthreads();

    const uint32_t ap_base = sSb + (uint32_t)(((wm * 32 + (lane & 15)) * 520 + (lane >> 4) * 8) * 2);
    const uint32_t bv_base = (uint32_t)((((lane & 7) + (lane >> 4) * 8 + wn * 16) * 136
                                        + ((lane >> 3) & 1) * 8) * 2);
    float accO[2][2][4];
#pragma unroll
    for (int mi = 0; mi < 2; ++mi)
#pragma unroll
        for (int ni = 0; ni < 2; ++ni)
#pragma unroll
            for (int r = 0; r < 4; ++r) accO[mi][ni][r] = 0.f;

    for (int c = 0; c < 4; ++c) {
        if (c + 1 < 4) load_v(c + 1, (c + 1) & 1);
        cpa_commit();
        cpa_wait<1>();
        __syncthreads();
        uint32_t svb = sKV + (uint32_t)((c & 1) * 18432);

#pragma unroll
        for (int ks = 0; ks < 8; ++ks) {
            const uint32_t kgo = (uint32_t)((c * 128 + ks * 16) * 2);
            const uint32_t ko = (uint32_t)(ks * 32);
            uint32_t af[2][4], bf[4];
            ldm4(af[0], ap_base + kgo);
            ldm4(af[1], ap_base + (uint32_t)(16 * 520 * 2) + kgo);
            ldm4(bf, svb + bv_base + ko);
#pragma unroll
            for (int mi = 0; mi < 2; ++mi) {
                mma16(accO[mi][0], af[mi], &bf[0]);
                mma16(accO[mi][1], af[mi], &bf[2]);
            }
        }
        __syncthreads();
    }

#pragma unroll
    for (int mi = 0; mi < 2; ++mi) {
#pragma unroll
        for (int ni = 0; ni < 2; ++ni) {
            int m = wm * 32 + mi * 16 + g;
            int n = wn * 16 + ni * 8 + 2 * t4;
            size_t rowg = (size_t)(b * 512 + qb * 64 + m);
            *(__half2*)&g_prelnh[rowg * 512 + h * 64 + n] =
                __float22half2_rn(make_float2(accO[mi][ni][0], accO[mi][ni][1]));
            *(__half2*)&g_prelnh[(rowg + 8) * 512 + h * 64 + n] =
                __float22half2_rn(make_float2(accO[mi][ni][2], accO[mi][ni][3]));
        }
    }
}

// ---------------- Kernel 3: LayerNorm (fp16 in, single fused reduction) ------
__global__ __launch_bounds__(256) void ln_kernel(
    const float* __restrict__ gamma, const float* __restrict__ beta,
    float* __restrict__ out)
{
    const int tid = threadIdx.x;
    const int rl = tid >> 6;
    const int ts = tid & 63;
    const int w = tid >> 5;
    const int row = blockIdx.x * 4 + rl;
    const __half* __restrict__ pr = g_prelnh + (size_t)row * 512;

    uint4 raw = *(const uint4*)(pr + ts * 8);
    __half2 hv[4];
    hv[0] = *(__half2*)&raw.x; hv[1] = *(__half2*)&raw.y;
    hv[2] = *(__half2*)&raw.z; hv[3] = *(__half2*)&raw.w;
    float v[8];
#pragma unroll
    for (int i = 0; i < 4; ++i) {
        float2 f = __half22float2(hv[i]);
        v[2 * i] = f.x; v[2 * i + 1] = f.y;
    }

    __shared__ float red[8], red2[8];
    float s = 0.f, sq = 0.f;
#pragma unroll
    for (int i = 0; i < 8; ++i) { s += v[i]; sq += v[i] * v[i]; }
#pragma unroll
    for (int o = 16; o > 0; o >>= 1) {
        s  += __shfl_xor_sync(0xffffffffu, s, o);
        sq += __shfl_xor_sync(0xffffffffu, sq, o);
    }
    if ((tid & 31) == 0) { red[w] = s; red2[w] = sq; }
    __syncthreads();
    float mu  = (red[rl * 2]  + red[rl * 2 + 1])  * (1.f / 512.f);
    float ex2 = (red2[rl * 2] + red2[rl * 2 + 1]) * (1.f / 512.f);
    float var = ex2 - mu * mu;
    float inv = rsqrtf(var + LN_EPS);

    float4 g0 = *(const float4*)(gamma + ts * 8);
    float4 g1 = *(const float4*)(gamma + ts * 8 + 4);
    float4 b0 = *(const float4*)(beta + ts * 8);
    float4 b1 = *(const float4*)(beta + ts * 8 + 4);
    float4 o0, o1;
    o0.x = g0.x * (v[0] - mu) * inv + b0.x;
    o0.y = g0.y * (v[1] - mu) * inv + b0.y;
    o0.z = g0.z * (v[2] - mu) * inv + b0.z;
    o0.w = g0.w * (v[3] - mu) * inv + b0.w;
    o1.x = g1.x * (v[4] - mu) * inv + b1.x;
    o1.y = g1.y * (v[5] - mu) * inv + b1.y;
    o1.z = g1.z * (v[6] - mu) * inv + b1.z;
    o1.w = g1.w * (v[7] - mu) * inv + b1.w;
    *(float4*)(out + (size_t)row * 512 + ts * 8) = o0;
    *(float4*)(out + (size_t)row * 512 + ts * 8 + 4) = o1;
}

// ---------------------------------------------------------------------------
extern "C" void kernel_launch(void* const* d_in, const int* in_sizes, int n_in,
                              void* d_out, int out_size)
{
    const float* x          = (const float*)d_in[0];
    const float* wq         = (const float*)d_in[1];
    const float* wk         = (const float*)d_in[2];
    const float* wv         = (const float*)d_in[3];
    const float* bias_table = (const float*)d_in[4];
    const float* gamma      = (const float*)d_in[5];
    const float* beta       = (const float*)d_in[6];
    float* out = (float*)d_out;

    cudaFuncSetAttribute(qkv_g,  cudaFuncAttributeMaxDynamicSharedMemorySize, QKV_SMEM);
    cudaFuncSetAttribute(attn_g, cudaFuncAttributeMaxDynamicSharedMemorySize, ATT_SMEM);

    cvt_w_kernel<<<384, 256>>>(wq, wk, wv);
    qkv_g<<<dim3(4, 128, 3), 256, QKV_SMEM>>>(x);
    attn_g<<<dim3(8, 256), 256, ATT_SMEM>>>(bias_table);
    ln_kernel<<<4096, 256>>>(gamma, beta, out);
}

// round 13
// speedup vs baseline: 1.1963x; 1.1963x over previous
#include <cuda_runtime.h>
#include <cuda_fp16.h>
#include <cstdint>

#define Hh 8
#define LN_EPS 1e-5f
#define SCALE 0.04419417382415922f  // 512^-0.5 (full C, as in source)

// ---------------- scratch (device globals) ----------------------------------
__device__ __half g_xh[(size_t)16384 * 512];      // fp16 x
__device__ __half g_wh[(size_t)3 * 512 * 512];    // fp16 wq|wk|wv
__device__ __half g_qh[(size_t)256 * 512 * 64];   // (b,h,l,d)
__device__ __half g_kh[(size_t)256 * 512 * 64];   // (b,h,l,d)
__device__ __half g_vh[(size_t)256 * 64 * 512];   // (b,h,d,l) transposed V
__device__ __half g_prelnh[(size_t)16384 * 512];  // fp16 pre-LN intermediate

// ---------------- helpers ---------------------------------------------------
__device__ __forceinline__ uint32_t s2u(const void* p) {
    uint32_t a;
    asm("{ .reg .u64 t; cvta.to.shared.u64 t, %1; cvt.u32.u64 %0, t; }" : "=r"(a) : "l"(p));
    return a;
}
__device__ __forceinline__ void cpa16(uint32_t s, const void* g) {
    asm volatile("cp.async.cg.shared.global [%0], [%1], 16;" :: "r"(s), "l"(g));
}
__device__ __forceinline__ void cpa_commit() { asm volatile("cp.async.commit_group;" ::: "memory"); }
template <int N>
__device__ __forceinline__ void cpa_wait() { asm volatile("cp.async.wait_group %0;" :: "n"(N) : "memory"); }

__device__ __forceinline__ void ldm4(uint32_t (&r)[4], uint32_t addr) {
    asm volatile("ldmatrix.sync.aligned.m8n8.x4.shared.b16 {%0,%1,%2,%3}, [%4];"
                 : "=r"(r[0]), "=r"(r[1]), "=r"(r[2]), "=r"(r[3]) : "r"(addr));
}
__device__ __forceinline__ void mma16(float (&c)[4], const uint32_t (&a)[4], const uint32_t* b) {
    asm volatile(
        "mma.sync.aligned.m16n8k16.row.col.f32.f16.f16.f32 "
        "{%0,%1,%2,%3}, {%4,%5,%6,%7}, {%8,%9}, {%0,%1,%2,%3};"
        : "+f"(c[0]), "+f"(c[1]), "+f"(c[2]), "+f"(c[3])
        : "r"(a[0]), "r"(a[1]), "r"(a[2]), "r"(a[3]), "r"(b[0]), "r"(b[1]));
}

// ---------------- Kernel 0: fp16 convert of x and weights --------------------
__global__ __launch_bounds__(256) void cvt_all_kernel(
    const float* __restrict__ x, const float* __restrict__ wq,
    const float* __restrict__ wk, const float* __restrict__ wv)
{
    int idx = blockIdx.x * 256 + threadIdx.x;   // 8-float group
    const int XG = 16384 * 512 / 8;             // 1048576
    const int WG = 512 * 512 / 8;               // 32768
    const float4* src; __half* dst;
    if (idx < XG) {
        src = (const float4*)x + (size_t)idx * 2;
        dst = g_xh + (size_t)idx * 8;
    } else {
        int j = idx - XG;
        int w = j / WG, r = j - w * WG;
        const float* s = (w == 0) ? wq : (w == 1) ? wk : wv;
        src = (const float4*)s + (size_t)r * 2;
        dst = g_wh + ((size_t)w * WG + r) * 8;
    }
    float4 a = src[0], b = src[1];
    __half2 h0 = __float22half2_rn(make_float2(a.x, a.y));
    __half2 h1 = __float22half2_rn(make_float2(a.z, a.w));
    __half2 h2 = __float22half2_rn(make_float2(b.x, b.y));
    __half2 h3 = __float22half2_rn(make_float2(b.z, b.w));
    uint4 o = make_uint4(*(uint32_t*)&h0, *(uint32_t*)&h1, *(uint32_t*)&h2, *(uint32_t*)&h3);
    *(uint4*)dst = o;
}

// ---------------- Kernel 1: QKV projection (fp16 mma, 3-stage pipeline) ------
// CTA 128x128, 8 warps (2m x 4n), warp tile 64x32. K-chunk 64, TRIPLE buffer.
#define QKV_SMEM 110592
__global__ __launch_bounds__(256, 2) void qkv_g(void)
{
    extern __shared__ __half smh[];
    const uint32_t sb = s2u(smh);
    const int tid = threadIdx.x;
    const int lane = tid & 31, warp = tid >> 5;
    const int wm = warp & 1, wn = warp >> 1;
    const int g = lane >> 2, t4 = lane & 3;
    const int which = blockIdx.z;
    const int m0 = blockIdx.y * 128;
    const int n0 = blockIdx.x * 128;

    const __half* __restrict__ A = g_xh + (size_t)m0 * 512;
    const __half* __restrict__ B = g_wh + (size_t)which * 262144 + (size_t)n0 * 512;

    constexpr int A_H = 128 * 72;
    constexpr int STAGE_H = 2 * A_H;

    const uint32_t a_base = (uint32_t)(((wm * 64 + (lane & 15)) * 72 + (lane >> 4) * 8) * 2);
    const uint32_t b_base = (uint32_t)(A_H * 2 +
        (((lane & 7) + (lane >> 4) * 8 + wn * 32) * 72 + ((lane >> 3) & 1) * 8) * 2);

    float acc[4][4][4];
#pragma unroll
    for (int mi = 0; mi < 4; ++mi)
#pragma unroll
        for (int ni = 0; ni < 4; ++ni)
#pragma unroll
            for (int r = 0; r < 4; ++r) acc[mi][ni][r] = 0.f;

    auto load_chunk = [&](int c, int buf) {
        uint32_t base = sb + (uint32_t)(buf * STAGE_H * 2);
#pragma unroll
        for (int i = 0; i < 8; ++i) {
            int idx = tid + i * 256;
            if (idx < 1024) {
                int r = idx >> 3, sg = idx & 7;
                cpa16(base + (uint32_t)((r * 72 + sg * 8) * 2),
                      A + (size_t)r * 512 + c * 64 + sg * 8);
            } else {
                int j = idx - 1024;
                int r = j >> 3, sg = j & 7;
                cpa16(base + (uint32_t)(A_H * 2 + (r * 72 + sg * 8) * 2),
                      B + (size_t)r * 512 + c * 64 + sg * 8);
            }
        }
    };

    load_chunk(0, 0);
    cpa_commit();
    load_chunk(1, 1);
    cpa_commit();

    for (int c = 0; c < 8; ++c) {
        if (c + 2 < 8) load_chunk(c + 2, (c + 2) % 3);
        cpa_commit();
        cpa_wait<2>();
        __syncthreads();
        uint32_t sa = sb + (uint32_t)((c % 3) * STAGE_H * 2);
#pragma unroll
        for (int ks = 0; ks < 4; ++ks) {
            const uint32_t ko = (uint32_t)(ks * 32);
            uint32_t af[4][4], bf0[4], bf1[4];
#pragma unroll
            for (int mi = 0; mi < 4; ++mi)
                ldm4(af[mi], sa + a_base + (uint32_t)(mi * 16 * 72 * 2) + ko);
            ldm4(bf0, sa + b_base + ko);
            ldm4(bf1, sa + b_base + (uint32_t)(16 * 72 * 2) + ko);
#pragma unroll
            for (int mi = 0; mi < 4; ++mi) {
                mma16(acc[mi][0], af[mi], &bf0[0]);
                mma16(acc[mi][1], af[mi], &bf0[2]);
                mma16(acc[mi][2], af[mi], &bf1[0]);
                mma16(acc[mi][3], af[mi], &bf1[2]);
            }
        }
        __syncthreads();
    }

    __half* sT = smh;   // 128 x 136 staging tile
    if (which <= 1) {
#pragma unroll
        for (int mi = 0; mi < 4; ++mi) {
#pragma unroll
            for (int ni = 0; ni < 4; ++ni) {
                int nl = wn * 32 + ni * 8 + 2 * t4;
                int ml = wm * 64 + mi * 16 + g;
                *(__half2*)&sT[ml * 136 + nl] =
                    __float22half2_rn(make_float2(acc[mi][ni][0], acc[mi][ni][1]));
                *(__half2*)&sT[(ml + 8) * 136 + nl] =
                    __float22half2_rn(make_float2(acc[mi][ni][2], acc[mi][ni][3]));
            }
        }
        __syncthreads();
        __half* out = (which == 0) ? g_qh : g_kh;
        int b = m0 >> 9, l0 = m0 & 511;
#pragma unroll
        for (int i = 0; i < 8; ++i) {
            int f = tid + i * 256;
            int row = f >> 4, seg = f & 15;
            uint4 v = *(const uint4*)&sT[row * 136 + seg * 8];
            int h = (n0 >> 6) + (seg >> 3);
            int d = (seg & 7) * 8;
            *(uint4*)&out[((size_t)(b * 8 + h) * 512 + l0 + row) * 64 + d] = v;
        }
    } else {
#pragma unroll
        for (int mi = 0; mi < 4; ++mi) {
#pragma unroll
            for (int ni = 0; ni < 4; ++ni) {
                int nl = wn * 32 + ni * 8 + 2 * t4;
                int ml = wm * 64 + mi * 16 + g;
                sT[nl * 136 + ml]           = __float2half_rn(acc[mi][ni][0]);
                sT[(nl + 1) * 136 + ml]     = __float2half_rn(acc[mi][ni][1]);
                sT[nl * 136 + ml + 8]       = __float2half_rn(acc[mi][ni][2]);
                sT[(nl + 1) * 136 + ml + 8] = __float2half_rn(acc[mi][ni][3]);
            }
        }
        __syncthreads();
        int b = m0 >> 9, l0 = m0 & 511;
#pragma unroll
        for (int i = 0; i < 8; ++i) {
            int f = tid + i * 256;
            int row = f >> 4, seg = f & 15;
            uint4 v = *(const uint4*)&sT[row * 136 + seg * 8];
            int n = n0 + row, h = n >> 6, d = n & 63;
            *(uint4*)&g_vh[(((size_t)(b * 8 + h)) * 64 + d) * 512 + l0 + seg * 8] = v;
        }
    }
}

// ---------------- Kernel 2: fused attention (fp16 S, occupancy 2) ------------
#define ATT_SMEM 114944
#define SS_OFF   9216
#define SKV_OFF  75776
#define SB_OFF   112640
__global__ __launch_bounds__(256, 2) void attn_g(const float* __restrict__ bias_table)
{
    extern __shared__ char smc[];
    const uint32_t sb = s2u(smc);
    const int tid = threadIdx.x;
    const int lane = tid & 31, warp = tid >> 5;
    const int wm = warp & 1, wn = warp >> 1;
    const int g = lane >> 2, t4 = lane & 3;
    const int qb = blockIdx.x;
    const int bh = blockIdx.y;
    const int b = bh >> 3, h = bh & 7;

    const __half* __restrict__ gq = g_qh + (size_t)bh * 32768 + (size_t)qb * 64 * 64;
    const __half* __restrict__ gk = g_kh + (size_t)bh * 32768;
    const __half* __restrict__ gv = g_vh + (size_t)bh * 32768;

    const uint32_t sQ = sb;
    const uint32_t sSb = sb + SS_OFF;
    const uint32_t sKV = sb + SKV_OFF;
    __half* sSh = (__half*)(smc + SS_OFF);
    float* sbias = (float*)(smc + SB_OFF);
    const int woff = 448 - qb * 64;

#pragma unroll
    for (int i = 0; i < 2; ++i) {
        int idx = tid + i * 256;
        int r = idx >> 3, sg = idx & 7;
        cpa16(sQ + (uint32_t)((r * 72 + sg * 8) * 2), gq + (size_t)r * 64 + sg * 8);
    }
#pragma unroll
    for (int i = 0; i < 3; ++i) {
        int j = tid + i * 256;
        if (j < 575) sbias[j] = bias_table[(size_t)(j + woff) * 8 + h];
    }
    cpa_commit();

    auto load_k = [&](int c, int buf) {
        uint32_t base = sKV + (uint32_t)(buf * 18432);
        const __half* src = gk + (size_t)c * 128 * 64;
#pragma unroll
        for (int i = 0; i < 4; ++i) {
            int idx = tid + i * 256;
            int r = idx >> 3, sg = idx & 7;
            cpa16(base + (uint32_t)((r * 72 + sg * 8) * 2), src + (size_t)r * 64 + sg * 8);
        }
    };
    load_k(0, 0);
    cpa_commit();

    const uint32_t aq_base = (uint32_t)(((wm * 32 + (lane & 15)) * 72 + (lane >> 4) * 8) * 2);
    const uint32_t bk_base = (uint32_t)((((lane & 7) + (lane >> 4) * 8 + wn * 32) * 72
                                        + ((lane >> 3) & 1) * 8) * 2);

    for (int c = 0; c < 4; ++c) {
        if (c + 1 < 4) load_k(c + 1, (c + 1) & 1);
        cpa_commit();
        cpa_wait<1>();
        __syncthreads();
        uint32_t skb = sKV + (uint32_t)((c & 1) * 18432);

        float acc[2][4][4];
#pragma unroll
        for (int mi = 0; mi < 2; ++mi)
#pragma unroll
            for (int ni = 0; ni < 4; ++ni)
#pragma unroll
                for (int r = 0; r < 4; ++r) acc[mi][ni][r] = 0.f;

#pragma unroll
        for (int ks = 0; ks < 4; ++ks) {
            const uint32_t ko = (uint32_t)(ks * 32);
            uint32_t af[2][4], bf0[4], bf1[4];
            ldm4(af[0], sQ + aq_base + ko);
            ldm4(af[1], sQ + aq_base + (uint32_t)(16 * 72 * 2) + ko);
            ldm4(bf0, skb + bk_base + ko);
            ldm4(bf1, skb + bk_base + (uint32_t)(16 * 72 * 2) + ko);
#pragma unroll
            for (int mi = 0; mi < 2; ++mi) {
                mma16(acc[mi][0], af[mi], &bf0[0]);
                mma16(acc[mi][1], af[mi], &bf0[2]);
                mma16(acc[mi][2], af[mi], &bf1[0]);
                mma16(acc[mi][3], af[mi], &bf1[2]);
            }
        }
#pragma unroll
        for (int mi = 0; mi < 2; ++mi) {
#pragma unroll
            for (int ni = 0; ni < 4; ++ni) {
                int ml = wm * 32 + mi * 16 + g;
                int col = c * 128 + wn * 32 + ni * 8 + 2 * t4;
                *(__half2*)&sSh[ml * 520 + col] =
                    __float22half2_rn(make_float2(acc[mi][ni][0] * SCALE, acc[mi][ni][1] * SCALE));
                *(__half2*)&sSh[(ml + 8) * 520 + col] =
                    __float22half2_rn(make_float2(acc[mi][ni][2] * SCALE, acc[mi][ni][3] * SCALE));
            }
        }
        __syncthreads();
    }

    auto load_v = [&](int c, int buf) {
        uint32_t base = sKV + (uint32_t)(buf * 18432);
        const __half* src = gv + (size_t)c * 128;
#pragma unroll
        for (int i = 0; i < 4; ++i) {
            int idx = tid + i * 256;
            int r = idx >> 4, sg = idx & 15;
            cpa16(base + (uint32_t)((r * 136 + sg * 8) * 2), src + (size_t)r * 512 + sg * 8);
        }
    };
    load_v(0, 0);
    cpa_commit();

    // softmax (no max-sub: |s| < 1) + post-softmax bias; P fp16 in-place
    {
        const int r0 = warp * 8;
#pragma unroll
        for (int rr = 0; rr < 8; ++rr) {
            const int r = r0 + rr;
            __half2* rowh = (__half2*)(sSh + (size_t)r * 520);
            float vals[16];
            float s = 0.f;
#pragma unroll
            for (int jj = 0; jj < 8; ++jj) {
                float2 fv = __half22float2(rowh[lane + 32 * jj]);
                vals[2 * jj]     = __expf(fv.x);
                vals[2 * jj + 1] = __expf(fv.y);
                s += vals[2 * jj] + vals[2 * jj + 1];
            }
#pragma unroll
            for (int o = 16; o > 0; o >>= 1) s += __shfl_xor_sync(0xffffffffu, s, o);
            float inv = 1.f / s;
            int bbase = 63 - r;
#pragma unroll
            for (int jj = 0; jj < 8; ++jj) {
                int col = 2 * lane + 64 * jj;
                float2 p;
                p.x = vals[2 * jj]     * inv + sbias[bbase + col];
                p.y = vals[2 * jj + 1] * inv + sbias[bbase + col + 1];
                rowh[lane + 32 * jj] = __float22half2_rn(p);
            }
        }
    }
    __syncthreads();

    const uint32_t ap_base = sSb + (uint32_t)(((wm * 32 + (lane & 15)) * 520 + (lane >> 4) * 8) * 2);
    const uint32_t bv_base = (uint32_t)((((lane & 7) + (lane >> 4) * 8 + wn * 16) * 136
                                        + ((lane >> 3) & 1) * 8) * 2);
    float accO[2][2][4];
#pragma unroll
    for (int mi = 0; mi < 2; ++mi)
#pragma unroll
        for (int ni = 0; ni < 2; ++ni)
#pragma unroll
            for (int r = 0; r < 4; ++r) accO[mi][ni][r] = 0.f;

    for (int c = 0; c < 4; ++c) {
        if (c + 1 < 4) load_v(c + 1, (c + 1) & 1);
        cpa_commit();
        cpa_wait<1>();
        __syncthreads();
        uint32_t svb = sKV + (uint32_t)((c & 1) * 18432);

#pragma unroll
        for (int ks = 0; ks < 8; ++ks) {
            const uint32_t kgo = (uint32_t)((c * 128 + ks * 16) * 2);
            const uint32_t ko = (uint32_t)(ks * 32);
            uint32_t af[2][4], bf[4];
            ldm4(af[0], ap_base + kgo);
            ldm4(af[1], ap_base + (uint32_t)(16 * 520 * 2) + kgo);
            ldm4(bf, svb + bv_base + ko);
#pragma unroll
            for (int mi = 0; mi < 2; ++mi) {
                mma16(accO[mi][0], af[mi], &bf[0]);
                mma16(accO[mi][1], af[mi], &bf[2]);
            }
        }
        __syncthreads();
    }

#pragma unroll
    for (int mi = 0; mi < 2; ++mi) {
#pragma unroll
        for (int ni = 0; ni < 2; ++ni) {
            int m = wm * 32 + mi * 16 + g;
            int n = wn * 16 + ni * 8 + 2 * t4;
            size_t rowg = (size_t)(b * 512 + qb * 64 + m);
            *(__half2*)&g_prelnh[rowg * 512 + h * 64 + n] =
                __float22half2_rn(make_float2(accO[mi][ni][0], accO[mi][ni][1]));
            *(__half2*)&g_prelnh[(rowg + 8) * 512 + h * 64 + n] =
                __float22half2_rn(make_float2(accO[mi][ni][2], accO[mi][ni][3]));
        }
    }
}

// ---------------- Kernel 3: LayerNorm (warp-per-row, no smem/syncthreads) ----
__global__ __launch_bounds__(256) void ln_kernel(
    const float* __restrict__ gamma, const float* __restrict__ beta,
    float* __restrict__ out)
{
    const int tid = threadIdx.x;
    const int lane = tid & 31, warp = tid >> 5;
    const int row = blockIdx.x * 8 + warp;
    const __half* __restrict__ pr = g_prelnh + (size_t)row * 512;

    // 32 lanes x 16 halves = 512
    uint4 raw0 = *(const uint4*)(pr + lane * 16);
    uint4 raw1 = *(const uint4*)(pr + lane * 16 + 8);
    float v[16];
    {
        const uint32_t* rw = (const uint32_t*)&raw0;
#pragma unroll
        for (int i = 0; i < 4; ++i) {
            float2 f = __half22float2(*(const __half2*)&rw[i]);
            v[2 * i] = f.x; v[2 * i + 1] = f.y;
        }
        const uint32_t* rw1 = (const uint32_t*)&raw1;
#pragma unroll
        for (int i = 0; i < 4; ++i) {
            float2 f = __half22float2(*(const __half2*)&rw1[i]);
            v[8 + 2 * i] = f.x; v[9 + 2 * i] = f.y;
        }
    }

    float s = 0.f, sq = 0.f;
#pragma unroll
    for (int i = 0; i < 16; ++i) { s += v[i]; sq += v[i] * v[i]; }
#pragma unroll
    for (int o = 16; o > 0; o >>= 1) {
        s  += __shfl_xor_sync(0xffffffffu, s, o);
        sq += __shfl_xor_sync(0xffffffffu, sq, o);
    }
    float mu  = s * (1.f / 512.f);
    float var = sq * (1.f / 512.f) - mu * mu;
    float inv = rsqrtf(var + LN_EPS);

    float* op = out + (size_t)row * 512 + lane * 16;
    const float* gp = gamma + lane * 16;
    const float* bp = beta + lane * 16;
#pragma unroll
    for (int q = 0; q < 4; ++q) {
        float4 gg = *(const float4*)(gp + q * 4);
        float4 bb = *(const float4*)(bp + q * 4);
        float4 o;
        o.x = gg.x * (v[q * 4 + 0] - mu) * inv + bb.x;
        o.y = gg.y * (v[q * 4 + 1] - mu) * inv + bb.y;
        o.z = gg.z * (v[q * 4 + 2] - mu) * inv + bb.z;
        o.w = gg.w * (v[q * 4 + 3] - mu) * inv + bb.w;
        *(float4*)(op + q * 4) = o;
    }
}

// ---------------------------------------------------------------------------
extern "C" void kernel_launch(void* const* d_in, const int* in_sizes, int n_in,
                              void* d_out, int out_size)
{
    const float* x          = (const float*)d_in[0];
    const float* wq         = (const float*)d_in[1];
    const float* wk         = (const float*)d_in[2];
    const float* wv         = (const float*)d_in[3];
    const float* bias_table = (const float*)d_in[4];
    const float* gamma      = (const float*)d_in[5];
    const float* beta       = (const float*)d_in[6];
    float* out = (float*)d_out;

    cudaFuncSetAttribute(qkv_g,  cudaFuncAttributeMaxDynamicSharedMemorySize, QKV_SMEM);
    cudaFuncSetAttribute(attn_g, cudaFuncAttributeMaxDynamicSharedMemorySize, ATT_SMEM);

    cvt_all_kernel<<<4480, 256>>>(x, wq, wk, wv);
    qkv_g<<<dim3(4, 128, 3), 256, QKV_SMEM>>>();
    attn_g<<<dim3(8, 256), 256, ATT_SMEM>>>(bias_table);
    ln_kernel<<<2048, 256>>>(gamma, beta, out);
}

// round 14
// speedup vs baseline: 1.2278x; 1.0264x over previous
#include <cuda_runtime.h>
#include <cuda_fp16.h>
#include <cstdint>

#define Hh 8
#define LN_EPS 1e-5f
#define SCALE 0.04419417382415922f  // 512^-0.5 (full C, as in source)

// ---------------- scratch (device globals) ----------------------------------
__device__ __half g_xh[(size_t)16384 * 512];      // fp16 x
__device__ __half g_wh[(size_t)3 * 512 * 512];    // fp16 wq|wk|wv
__device__ __half g_qh[(size_t)256 * 512 * 64];   // (b,h,l,d)
__device__ __half g_kh[(size_t)256 * 512 * 64];   // (b,h,l,d)
__device__ __half g_vh[(size_t)256 * 64 * 512];   // (b,h,d,l) transposed V
__device__ __half g_prelnh[(size_t)16384 * 512];  // fp16 pre-LN intermediate

// ---------------- helpers ---------------------------------------------------
__device__ __forceinline__ uint32_t s2u(const void* p) {
    uint32_t a;
    asm("{ .reg .u64 t; cvta.to.shared.u64 t, %1; cvt.u32.u64 %0, t; }" : "=r"(a) : "l"(p));
    return a;
}
__device__ __forceinline__ void cpa16(uint32_t s, const void* g) {
    asm volatile("cp.async.cg.shared.global [%0], [%1], 16;" :: "r"(s), "l"(g));
}
__device__ __forceinline__ void cpa_commit() { asm volatile("cp.async.commit_group;" ::: "memory"); }
template <int N>
__device__ __forceinline__ void cpa_wait() { asm volatile("cp.async.wait_group %0;" :: "n"(N) : "memory"); }

__device__ __forceinline__ void ldm4(uint32_t (&r)[4], uint32_t addr) {
    asm volatile("ldmatrix.sync.aligned.m8n8.x4.shared.b16 {%0,%1,%2,%3}, [%4];"
                 : "=r"(r[0]), "=r"(r[1]), "=r"(r[2]), "=r"(r[3]) : "r"(addr));
}
__device__ __forceinline__ void mma16(float (&c)[4], const uint32_t (&a)[4], const uint32_t* b) {
    asm volatile(
        "mma.sync.aligned.m16n8k16.row.col.f32.f16.f16.f32 "
        "{%0,%1,%2,%3}, {%4,%5,%6,%7}, {%8,%9}, {%0,%1,%2,%3};"
        : "+f"(c[0]), "+f"(c[1]), "+f"(c[2]), "+f"(c[3])
        : "r"(a[0]), "r"(a[1]), "r"(a[2]), "r"(a[3]), "r"(b[0]), "r"(b[1]));
}
__device__ __forceinline__ float4 ldcs4(const float* p) {
    float4 v;
    asm volatile("ld.global.cs.v4.f32 {%0,%1,%2,%3}, [%4];"
                 : "=f"(v.x), "=f"(v.y), "=f"(v.z), "=f"(v.w) : "l"(p));
    return v;
}
__device__ __forceinline__ void stcs4(float* p, float4 v) {
    asm volatile("st.global.cs.v4.f32 [%0], {%1,%2,%3,%4};"
                 :: "l"(p), "f"(v.x), "f"(v.y), "f"(v.z), "f"(v.w) : "memory");
}

// ---------------- Kernel 0: fp16 convert of x and weights --------------------
__global__ __launch_bounds__(256) void cvt_all_kernel(
    const float* __restrict__ x, const float* __restrict__ wq,
    const float* __restrict__ wk, const float* __restrict__ wv)
{
    int idx = blockIdx.x * 256 + threadIdx.x;   // 8-float group
    const int XG = 16384 * 512 / 8;             // 1048576
    const int WG = 512 * 512 / 8;               // 32768
    const float* srcp; __half* dst;
    if (idx < XG) {
        srcp = x + (size_t)idx * 8;
        dst = g_xh + (size_t)idx * 8;
    } else {
        int j = idx - XG;
        int w = j / WG, r = j - w * WG;
        const float* s = (w == 0) ? wq : (w == 1) ? wk : wv;
        srcp = s + (size_t)r * 8;
        dst = g_wh + ((size_t)w * WG + r) * 8;
    }
    float4 a = ldcs4(srcp);
    float4 b = ldcs4(srcp + 4);
    __half2 h0 = __float22half2_rn(make_float2(a.x, a.y));
    __half2 h1 = __float22half2_rn(make_float2(a.z, a.w));
    __half2 h2 = __float22half2_rn(make_float2(b.x, b.y));
    __half2 h3 = __float22half2_rn(make_float2(b.z, b.w));
    uint4 o = make_uint4(*(uint32_t*)&h0, *(uint32_t*)&h1, *(uint32_t*)&h2, *(uint32_t*)&h3);
    *(uint4*)dst = o;
}

// ---------------- Kernel 1: QKV projection (fp16 mma, 3-stage pipeline) ------
// CTA 128x128, 8 warps (2m x 4n), warp tile 64x32. K-chunk 64, TRIPLE buffer.
#define QKV_SMEM 110592
__global__ __launch_bounds__(256, 2) void qkv_g(void)
{
    extern __shared__ __half smh[];
    const uint32_t sb = s2u(smh);
    const int tid = threadIdx.x;
    const int lane = tid & 31, warp = tid >> 5;
    const int wm = warp & 1, wn = warp >> 1;
    const int g = lane >> 2, t4 = lane & 3;
    const int which = blockIdx.z;
    const int m0 = blockIdx.y * 128;
    const int n0 = blockIdx.x * 128;

    const __half* __restrict__ A = g_xh + (size_t)m0 * 512;
    const __half* __restrict__ B = g_wh + (size_t)which * 262144 + (size_t)n0 * 512;

    constexpr int A_H = 128 * 72;
    constexpr int STAGE_H = 2 * A_H;

    const uint32_t a_base = (uint32_t)(((wm * 64 + (lane & 15)) * 72 + (lane >> 4) * 8) * 2);
    const uint32_t b_base = (uint32_t)(A_H * 2 +
        (((lane & 7) + (lane >> 4) * 8 + wn * 32) * 72 + ((lane >> 3) & 1) * 8) * 2);

    float acc[4][4][4];
#pragma unroll
    for (int mi = 0; mi < 4; ++mi)
#pragma unroll
        for (int ni = 0; ni < 4; ++ni)
#pragma unroll
            for (int r = 0; r < 4; ++r) acc[mi][ni][r] = 0.f;

    auto load_chunk = [&](int c, int buf) {
        uint32_t base = sb + (uint32_t)(buf * STAGE_H * 2);
#pragma unroll
        for (int i = 0; i < 8; ++i) {
            int idx = tid + i * 256;
            if (idx < 1024) {
                int r = idx >> 3, sg = idx & 7;
                cpa16(base + (uint32_t)((r * 72 + sg * 8) * 2),
                      A + (size_t)r * 512 + c * 64 + sg * 8);
            } else {
                int j = idx - 1024;
                int r = j >> 3, sg = j & 7;
                cpa16(base + (uint32_t)(A_H * 2 + (r * 72 + sg * 8) * 2),
                      B + (size_t)r * 512 + c * 64 + sg * 8);
            }
        }
    };

    load_chunk(0, 0);
    cpa_commit();
    load_chunk(1, 1);
    cpa_commit();

    for (int c = 0; c < 8; ++c) {
        if (c + 2 < 8) load_chunk(c + 2, (c + 2) % 3);
        cpa_commit();
        cpa_wait<2>();
        __syncthreads();
        uint32_t sa = sb + (uint32_t)((c % 3) * STAGE_H * 2);
#pragma unroll
        for (int ks = 0; ks < 4; ++ks) {
            const uint32_t ko = (uint32_t)(ks * 32);
            uint32_t af[4][4], bf0[4], bf1[4];
#pragma unroll
            for (int mi = 0; mi < 4; ++mi)
                ldm4(af[mi], sa + a_base + (uint32_t)(mi * 16 * 72 * 2) + ko);
            ldm4(bf0, sa + b_base + ko);
            ldm4(bf1, sa + b_base + (uint32_t)(16 * 72 * 2) + ko);
#pragma unroll
            for (int mi = 0; mi < 4; ++mi) {
                mma16(acc[mi][0], af[mi], &bf0[0]);
                mma16(acc[mi][1], af[mi], &bf0[2]);
                mma16(acc[mi][2], af[mi], &bf1[0]);
                mma16(acc[mi][3], af[mi], &bf1[2]);
            }
        }
        __syncthreads();
    }

    __half* sT = smh;   // 128 x 136 staging tile
    if (which <= 1) {
#pragma unroll
        for (int mi = 0; mi < 4; ++mi) {
#pragma unroll
            for (int ni = 0; ni < 4; ++ni) {
                int nl = wn * 32 + ni * 8 + 2 * t4;
                int ml = wm * 64 + mi * 16 + g;
                *(__half2*)&sT[ml * 136 + nl] =
                    __float22half2_rn(make_float2(acc[mi][ni][0], acc[mi][ni][1]));
                *(__half2*)&sT[(ml + 8) * 136 + nl] =
                    __float22half2_rn(make_float2(acc[mi][ni][2], acc[mi][ni][3]));
            }
        }
        __syncthreads();
        __half* out = (which == 0) ? g_qh : g_kh;
        int b = m0 >> 9, l0 = m0 & 511;
#pragma unroll
        for (int i = 0; i < 8; ++i) {
            int f = tid + i * 256;
            int row = f >> 4, seg = f & 15;
            uint4 v = *(const uint4*)&sT[row * 136 + seg * 8];
            int h = (n0 >> 6) + (seg >> 3);
            int d = (seg & 7) * 8;
            *(uint4*)&out[((size_t)(b * 8 + h) * 512 + l0 + row) * 64 + d] = v;
        }
    } else {
#pragma unroll
        for (int mi = 0; mi < 4; ++mi) {
#pragma unroll
            for (int ni = 0; ni < 4; ++ni) {
                int nl = wn * 32 + ni * 8 + 2 * t4;
                int ml = wm * 64 + mi * 16 + g;
                sT[nl * 136 + ml]           = __float2half_rn(acc[mi][ni][0]);
                sT[(nl + 1) * 136 + ml]     = __float2half_rn(acc[mi][ni][1]);
                sT[nl * 136 + ml + 8]       = __float2half_rn(acc[mi][ni][2]);
                sT[(nl + 1) * 136 + ml + 8] = __float2half_rn(acc[mi][ni][3]);
            }
        }
        __syncthreads();
        int b = m0 >> 9, l0 = m0 & 511;
#pragma unroll
        for (int i = 0; i < 8; ++i) {
            int f = tid + i * 256;
            int row = f >> 4, seg = f & 15;
            uint4 v = *(const uint4*)&sT[row * 136 + seg * 8];
            int n = n0 + row, h = n >> 6, d = n & 63;
            *(uint4*)&g_vh[(((size_t)(b * 8 + h)) * 64 + d) * 512 + l0 + seg * 8] = v;
        }
    }
}

// ---------------- Kernel 2: fused attention (fp16 S, occupancy 2) ------------
#define ATT_SMEM 114944
#define SS_OFF   9216
#define SKV_OFF  75776
#define SB_OFF   112640
__global__ __launch_bounds__(256, 2) void attn_g(const float* __restrict__ bias_table)
{
    extern __shared__ char smc[];
    const uint32_t sb = s2u(smc);
    const int tid = threadIdx.x;
    const int lane = tid & 31, warp = tid >> 5;
    const int wm = warp & 1, wn = warp >> 1;
    const int g = lane >> 2, t4 = lane & 3;
    const int qb = blockIdx.x;
    const int bh = blockIdx.y;
    const int b = bh >> 3, h = bh & 7;

    const __half* __restrict__ gq = g_qh + (size_t)bh * 32768 + (size_t)qb * 64 * 64;
    const __half* __restrict__ gk = g_kh + (size_t)bh * 32768;
    const __half* __restrict__ gv = g_vh + (size_t)bh * 32768;

    const uint32_t sQ = sb;
    const uint32_t sSb = sb + SS_OFF;
    const uint32_t sKV = sb + SKV_OFF;
    __half* sSh = (__half*)(smc + SS_OFF);
    float* sbias = (float*)(smc + SB_OFF);
    const int woff = 448 - qb * 64;

#pragma unroll
    for (int i = 0; i < 2; ++i) {
        int idx = tid + i * 256;
        int r = idx >> 3, sg = idx & 7;
        cpa16(sQ + (uint32_t)((r * 72 + sg * 8) * 2), gq + (size_t)r * 64 + sg * 8);
    }
#pragma unroll
    for (int i = 0; i < 3; ++i) {
        int j = tid + i * 256;
        if (j < 575) sbias[j] = bias_table[(size_t)(j + woff) * 8 + h];
    }
    cpa_commit();

    auto load_k = [&](int c, int buf) {
        uint32_t base = sKV + (uint32_t)(buf * 18432);
        const __half* src = gk + (size_t)c * 128 * 64;
#pragma unroll
        for (int i = 0; i < 4; ++i) {
            int idx = tid + i * 256;
            int r = idx >> 3, sg = idx & 7;
            cpa16(base + (uint32_t)((r * 72 + sg * 8) * 2), src + (size_t)r * 64 + sg * 8);
        }
    };
    load_k(0, 0);
    cpa_commit();

    const uint32_t aq_base = (uint32_t)(((wm * 32 + (lane & 15)) * 72 + (lane >> 4) * 8) * 2);
    const uint32_t bk_base = (uint32_t)((((lane & 7) + (lane >> 4) * 8 + wn * 32) * 72
                                        + ((lane >> 3) & 1) * 8) * 2);

    for (int c = 0; c < 4; ++c) {
        if (c + 1 < 4) load_k(c + 1, (c + 1) & 1);
        cpa_commit();
        cpa_wait<1>();
        __syncthreads();
        uint32_t skb = sKV + (uint32_t)((c & 1) * 18432);

        float acc[2][4][4];
#pragma unroll
        for (int mi = 0; mi < 2; ++mi)
#pragma unroll
            for (int ni = 0; ni < 4; ++ni)
#pragma unroll
                for (int r = 0; r < 4; ++r) acc[mi][ni][r] = 0.f;

#pragma unroll
        for (int ks = 0; ks < 4; ++ks) {
            const uint32_t ko = (uint32_t)(ks * 32);
            uint32_t af[2][4], bf0[4], bf1[4];
            ldm4(af[0], sQ + aq_base + ko);
            ldm4(af[1], sQ + aq_base + (uint32_t)(16 * 72 * 2) + ko);
            ldm4(bf0, skb + bk_base + ko);
            ldm4(bf1, skb + bk_base + (uint32_t)(16 * 72 * 2) + ko);
#pragma unroll
            for (int mi = 0; mi < 2; ++mi) {
                mma16(acc[mi][0], af[mi], &bf0[0]);
                mma16(acc[mi][1], af[mi], &bf0[2]);
                mma16(acc[mi][2], af[mi], &bf1[0]);
                mma16(acc[mi][3], af[mi], &bf1[2]);
            }
        }
#pragma unroll
        for (int mi = 0; mi < 2; ++mi) {
#pragma unroll
            for (int ni = 0; ni < 4; ++ni) {
                int ml = wm * 32 + mi * 16 + g;
                int col = c * 128 + wn * 32 + ni * 8 + 2 * t4;
                *(__half2*)&sSh[ml * 520 + col] =
                    __float22half2_rn(make_float2(acc[mi][ni][0] * SCALE, acc[mi][ni][1] * SCALE));
                *(__half2*)&sSh[(ml + 8) * 520 + col] =
                    __float22half2_rn(make_float2(acc[mi][ni][2] * SCALE, acc[mi][ni][3] * SCALE));
            }
        }
        __syncthreads();
    }

    auto load_v = [&](int c, int buf) {
        uint32_t base = sKV + (uint32_t)(buf * 18432);
        const __half* src = gv + (size_t)c * 128;
#pragma unroll
        for (int i = 0; i < 4; ++i) {
            int idx = tid + i * 256;
            int r = idx >> 4, sg = idx & 15;
            cpa16(base + (uint32_t)((r * 136 + sg * 8) * 2), src + (size_t)r * 512 + sg * 8);
        }
    };
    load_v(0, 0);
    cpa_commit();

    // softmax (no max-sub: |s| < 1) + post-softmax bias; P fp16 in-place
    {
        const int r0 = warp * 8;
#pragma unroll
        for (int rr = 0; rr < 8; ++rr) {
            const int r = r0 + rr;
            __half2* rowh = (__half2*)(sSh + (size_t)r * 520);
            float vals[16];
            float s = 0.f;
#pragma unroll
            for (int jj = 0; jj < 8; ++jj) {
                float2 fv = __half22float2(rowh[lane + 32 * jj]);
                vals[2 * jj]     = __expf(fv.x);
                vals[2 * jj + 1] = __expf(fv.y);
                s += vals[2 * jj] + vals[2 * jj + 1];
            }
#pragma unroll
            for (int o = 16; o > 0; o >>= 1) s += __shfl_xor_sync(0xffffffffu, s, o);
            float inv = 1.f / s;
            int bbase = 63 - r;
#pragma unroll
            for (int jj = 0; jj < 8; ++jj) {
                int col = 2 * lane + 64 * jj;
                float2 p;
                p.x = vals[2 * jj]     * inv + sbias[bbase + col];
                p.y = vals[2 * jj + 1] * inv + sbias[bbase + col + 1];
                rowh[lane + 32 * jj] = __float22half2_rn(p);
            }
        }
    }
    __syncthreads();

    const uint32_t ap_base = sSb + (uint32_t)(((wm * 32 + (lane & 15)) * 520 + (lane >> 4) * 8) * 2);
    const uint32_t bv_base = (uint32_t)((((lane & 7) + (lane >> 4) * 8 + wn * 16) * 136
                                        + ((lane >> 3) & 1) * 8) * 2);
    float accO[2][2][4];
#pragma unroll
    for (int mi = 0; mi < 2; ++mi)
#pragma unroll
        for (int ni = 0; ni < 2; ++ni)
#pragma unroll
            for (int r = 0; r < 4; ++r) accO[mi][ni][r] = 0.f;

    for (int c = 0; c < 4; ++c) {
        if (c + 1 < 4) load_v(c + 1, (c + 1) & 1);
        cpa_commit();
        cpa_wait<1>();
        __syncthreads();
        uint32_t svb = sKV + (uint32_t)((c & 1) * 18432);

#pragma unroll
        for (int ks = 0; ks < 8; ++ks) {
            const uint32_t kgo = (uint32_t)((c * 128 + ks * 16) * 2);
            const uint32_t ko = (uint32_t)(ks * 32);
            uint32_t af[2][4], bf[4];
            ldm4(af[0], ap_base + kgo);
            ldm4(af[1], ap_base + (uint32_t)(16 * 520 * 2) + kgo);
            ldm4(bf, svb + bv_base + ko);
#pragma unroll
            for (int mi = 0; mi < 2; ++mi) {
                mma16(accO[mi][0], af[mi], &bf[0]);
                mma16(accO[mi][1], af[mi], &bf[2]);
            }
        }
        __syncthreads();
    }

#pragma unroll
    for (int mi = 0; mi < 2; ++mi) {
#pragma unroll
        for (int ni = 0; ni < 2; ++ni) {
            int m = wm * 32 + mi * 16 + g;
            int n = wn * 16 + ni * 8 + 2 * t4;
            size_t rowg = (size_t)(b * 512 + qb * 64 + m);
            *(__half2*)&g_prelnh[rowg * 512 + h * 64 + n] =
                __float22half2_rn(make_float2(accO[mi][ni][0], accO[mi][ni][1]));
            *(__half2*)&g_prelnh[(rowg + 8) * 512 + h * 64 + n] =
                __float22half2_rn(make_float2(accO[mi][ni][2], accO[mi][ni][3]));
        }
    }
}

// ---------------- Kernel 3: LayerNorm (R11 shape + streaming stores) ---------
__global__ __launch_bounds__(256) void ln_kernel(
    const float* __restrict__ gamma, const float* __restrict__ beta,
    float* __restrict__ out)
{
    const int tid = threadIdx.x;
    const int rl = tid >> 6;          // 0..3 row within CTA
    const int ts = tid & 63;          // 64 threads per row, 8 halves each
    const int w = tid >> 5;
    const int row = blockIdx.x * 4 + rl;
    const __half* __restrict__ pr = g_prelnh + (size_t)row * 512;

    uint4 raw = *(const uint4*)(pr + ts * 8);
    __half2 hv[4];
    hv[0] = *(__half2*)&raw.x; hv[1] = *(__half2*)&raw.y;
    hv[2] = *(__half2*)&raw.z; hv[3] = *(__half2*)&raw.w;
    float v[8];
#pragma unroll
    for (int i = 0; i < 4; ++i) {
        float2 f = __half22float2(hv[i]);
        v[2 * i] = f.x; v[2 * i + 1] = f.y;
    }

    __shared__ float red[8], red2[8];
    float s = 0.f, sq = 0.f;
#pragma unroll
    for (int i = 0; i < 8; ++i) { s += v[i]; sq += v[i] * v[i]; }
#pragma unroll
    for (int o = 16; o > 0; o >>= 1) {
        s  += __shfl_xor_sync(0xffffffffu, s, o);
        sq += __shfl_xor_sync(0xffffffffu, sq, o);
    }
    if ((tid & 31) == 0) { red[w] = s; red2[w] = sq; }
    __syncthreads();
    float mu  = (red[rl * 2]  + red[rl * 2 + 1])  * (1.f / 512.f);
    float ex2 = (red2[rl * 2] + red2[rl * 2 + 1]) * (1.f / 512.f);
    float var = ex2 - mu * mu;
    float inv = rsqrtf(var + LN_EPS);

    float4 g0 = *(const float4*)(gamma + ts * 8);
    float4 g1 = *(const float4*)(gamma + ts * 8 + 4);
    float4 b0 = *(const float4*)(beta + ts * 8);
    float4 b1 = *(const float4*)(beta + ts * 8 + 4);
    float4 o0, o1;
    o0.x = g0.x * (v[0] - mu) * inv + b0.x;
    o0.y = g0.y * (v[1] - mu) * inv + b0.y;
    o0.z = g0.z * (v[2] - mu) * inv + b0.z;
    o0.w = g0.w * (v[3] - mu) * inv + b0.w;
    o1.x = g1.x * (v[4] - mu) * inv + b1.x;
    o1.y = g1.y * (v[5] - mu) * inv + b1.y;
    o1.z = g1.z * (v[6] - mu) * inv + b1.z;
    o1.w = g1.w * (v[7] - mu) * inv + b1.w;
    stcs4(out + (size_t)row * 512 + ts * 8, o0);
    stcs4(out + (size_t)row * 512 + ts * 8 + 4, o1);
}

// ---------------------------------------------------------------------------
extern "C" void kernel_launch(void* const* d_in, const int* in_sizes, int n_in,
                              void* d_out, int out_size)
{
    const float* x          = (const float*)d_in[0];
    const float* wq         = (const float*)d_in[1];
    const float* wk         = (const float*)d_in[2];
    const float* wv         = (const float*)d_in[3];
    const float* bias_table = (const float*)d_in[4];
    const float* gamma      = (const float*)d_in[5];
    const float* beta       = (const float*)d_in[6];
    float* out = (float*)d_out;

    cudaFuncSetAttribute(qkv_g,  cudaFuncAttributeMaxDynamicSharedMemorySize, QKV_SMEM);
    cudaFuncSetAttribute(attn_g, cudaFuncAttributeMaxDynamicSharedMemorySize, ATT_SMEM);

    cvt_all_kernel<<<4480, 256>>>(x, wq, wk, wv);
    qkv_g<<<dim3(4, 128, 3), 256, QKV_SMEM>>>();
    attn_g<<<dim3(8, 256), 256, ATT_SMEM>>>(bias_table);
    ln_kernel<<<4096, 256>>>(gamma, beta, out);
}